// round 15
// baseline (speedup 1.0000x reference)
#include <cuda_runtime.h>
#include <cstdint>

#define BB 8
#define SS 2048
#define DD 512
#define HH 512

// ---------------- scratch (device globals; no cudaMalloc allowed) ----------------
__device__ float g_Wx[(size_t)BB * SS * DD];          //  32 MB
__device__ float g_sc[(size_t)BB * SS * SS];          // 134 MB
__device__ float g_rinraw[(size_t)BB * SS * 2 * DD];  //  64 MB
__device__ float g_rin[(size_t)BB * SS * 2 * DD];     //  64 MB
__device__ float g_xwf[(size_t)BB * SS * 3 * HH];     //  96 MB
__device__ float g_xwb[(size_t)BB * SS * 3 * HH];     //  96 MB
__device__ float g_xwfT[(size_t)3 * HH * BB * SS];    //  96 MB (transposed [g*H+j][b*S+t])
__device__ float g_xwbT[(size_t)3 * HH * BB * SS];    //  96 MB
__device__ float g_hcat[(size_t)BB * SS * 2 * HH];    //  64 MB
__device__ float g_hcatT[(size_t)2 * HH * BB * SS];   //  64 MB (transposed)
__device__ unsigned long long g_h2[2][2][HH * BB];    // {tag,h} atoms, [phase][dir][j*8+b]

// =====================================================================
// tf32 helpers
// =====================================================================
__device__ __forceinline__ uint32_t f2tf(float f) {
    uint32_t u; asm("cvt.rna.tf32.f32 %0, %1;" : "=r"(u) : "f"(f)); return u;
}
__device__ __forceinline__ void mma_tf32(float* c, const uint32_t* a, uint32_t b0, uint32_t b1) {
    asm volatile(
        "mma.sync.aligned.m16n8k8.row.col.f32.tf32.tf32.f32 "
        "{%0,%1,%2,%3}, {%4,%5,%6,%7}, {%8,%9}, {%0,%1,%2,%3};\n"
        : "+f"(c[0]), "+f"(c[1]), "+f"(c[2]), "+f"(c[3])
        : "r"(a[0]), "r"(a[1]), "r"(a[2]), "r"(a[3]), "r"(b0), "r"(b1));
}
__device__ __forceinline__ uint32_t smem_u32(const void* p) {
    uint32_t a;
    asm("{ .reg .u64 t; cvta.to.shared.u64 t, %1; cvt.u32.u64 %0, t; }" : "=r"(a) : "l"(p));
    return a;
}
__device__ __forceinline__ unsigned long long ldrel64(const unsigned long long* p) {
    unsigned long long v;
    asm volatile("ld.relaxed.gpu.u64 %0, [%1];" : "=l"(v) : "l"(p));
    return v;
}
__device__ __forceinline__ void strel64(unsigned long long* p, unsigned long long v) {
    asm volatile("st.relaxed.gpu.u64 [%0], %1;" :: "l"(p), "l"(v) : "memory");
}
#define CP_ASYNC16(dst, src) \
    asm volatile("cp.async.cg.shared.global [%0], [%1], 16;" :: "r"(dst), "l"(src))
#define CP_COMMIT() asm volatile("cp.async.commit_group;" ::: "memory")
#define CP_WAIT1()  asm volatile("cp.async.wait_group 1;" ::: "memory")

// =====================================================================
// tf32 mma.sync GEMM with 3-stage cp.async pipeline (unchanged from R5/R7).
// =====================================================================
template <int BMODE, int SPLIT, int EPI>
__global__ void
__launch_bounds__(256, SPLIT ? 1 : 2)
pip_gemm(const float* __restrict__ A, const float* __restrict__ B,
         float* __restrict__ C, int M, int N, int K,
         int lda, int ldb, int ldc,
         long sA, long sB, long sC,
         const float* __restrict__ bias,
         const float* __restrict__ R, int ldr)
{
    A += (long)blockIdx.z * sA;
    B += (long)blockIdx.z * sB;
    C += (long)blockIdx.z * sC;

    extern __shared__ float sm[];
    const uint32_t sbase = smem_u32(sm);

    const int tid  = threadIdx.x;
    const int lane = tid & 31;
    const int warp = tid >> 5;
    const int gid  = lane >> 2;
    const int tig  = lane & 3;
    const int wm   = (warp >> 2) * 64;
    const int wn   = (warp & 3) * 32;
    const int bm   = blockIdx.y * 128;
    const int bn   = blockIdx.x * 128;
    const int nk   = K >> 5;

    float acc[4][4][4];
#pragma unroll
    for (int mt = 0; mt < 4; ++mt)
#pragma unroll
        for (int nt = 0; nt < 4; ++nt)
#pragma unroll
            for (int q = 0; q < 4; ++q) acc[mt][nt][q] = 0.f;

    int b1off0[4], b1off1[4];
    if (BMODE == 1) {
#pragma unroll
        for (int nt = 0; nt < 4; ++nt) {
            const int n = wn + nt * 8 + gid;
            b1off0[nt] = tig * 128       + ((((n >> 2) ^ (tig << 2)) << 2) + (n & 3));
            b1off1[nt] = (tig + 4) * 128 + ((((n >> 2) ^ ((tig + 4) << 2)) << 2) + (n & 3));
        }
    }

    const int arow = tid >> 3, ac4 = tid & 7;

#define ISSUE(kt)                                                             \
    {                                                                         \
        if ((kt) < nk) {                                                      \
            const uint32_t sa = sbase + ((kt) % 3) * 32768;                   \
            const uint32_t sb = sa + 16384;                                   \
            _Pragma("unroll")                                                 \
            for (int i = 0; i < 4; ++i) {                                     \
                const int row = arow + 32 * i;                                \
                const uint32_t dst = sa + (uint32_t)(row * 32 + ((ac4 ^ (row & 7)) << 2)) * 4; \
                CP_ASYNC16(dst, A + (size_t)(bm + row) * lda + (kt) * 32 + ac4 * 4); \
            }                                                                 \
            if (BMODE == 0) {                                                 \
                _Pragma("unroll")                                             \
                for (int i = 0; i < 4; ++i) {                                 \
                    const int row = arow + 32 * i;                            \
                    const uint32_t dst = sb + (uint32_t)(row * 32 + ((ac4 ^ (row & 7)) << 2)) * 4; \
                    CP_ASYNC16(dst, B + (size_t)(bn + row) * ldb + (kt) * 32 + ac4 * 4); \
                }                                                             \
            } else {                                                          \
                _Pragma("unroll")                                             \
                for (int i = 0; i < 4; ++i) {                                 \
                    const int idx = tid + 256 * i;                            \
                    const int row = idx >> 5, c4 = idx & 31;                  \
                    const uint32_t dst = sb + (uint32_t)(row * 128 + ((c4 ^ ((row & 7) << 2)) << 2)) * 4; \
                    CP_ASYNC16(dst, B + (size_t)((kt) * 32 + row) * ldb + bn + c4 * 4); \
                }                                                             \
            }                                                                 \
        }                                                                     \
        CP_COMMIT();                                                          \
    }

    ISSUE(0);
    ISSUE(1);

    for (int kt = 0; kt < nk; ++kt) {
        CP_WAIT1();
        __syncthreads();

        const float* pa = sm + (kt % 3) * 8192;
        const float* pb = pa + 4096;

#pragma unroll
        for (int ks = 0; ks < 4; ++ks) {
            const int s0 = tig + (((2 * ks)     ^ gid) << 2);
            const int s1 = tig + (((2 * ks + 1) ^ gid) << 2);

            float af[4][4];
#pragma unroll
            for (int mt = 0; mt < 4; ++mt) {
                const int r0 = (wm + mt * 16 + gid) * 32;
                const int r1 = r0 + 256;
                af[mt][0] = pa[r0 + s0];
                af[mt][1] = pa[r1 + s0];
                af[mt][2] = pa[r0 + s1];
                af[mt][3] = pa[r1 + s1];
            }
            float bf[4][2];
#pragma unroll
            for (int nt = 0; nt < 4; ++nt) {
                if (BMODE == 0) {
                    const int nrow = (wn + nt * 8 + gid) * 32;
                    bf[nt][0] = pb[nrow + s0];
                    bf[nt][1] = pb[nrow + s1];
                } else {
                    bf[nt][0] = pb[b1off0[nt] + ks * 1024];
                    bf[nt][1] = pb[b1off1[nt] + ks * 1024];
                }
            }

            if (!SPLIT) {
                uint32_t ah[4][4], bh[4][2];
#pragma unroll
                for (int mt = 0; mt < 4; ++mt)
#pragma unroll
                    for (int q = 0; q < 4; ++q) ah[mt][q] = f2tf(af[mt][q]);
#pragma unroll
                for (int nt = 0; nt < 4; ++nt) {
                    bh[nt][0] = f2tf(bf[nt][0]);
                    bh[nt][1] = f2tf(bf[nt][1]);
                }
#pragma unroll
                for (int mt = 0; mt < 4; ++mt)
#pragma unroll
                    for (int nt = 0; nt < 4; ++nt)
                        mma_tf32(acc[mt][nt], ah[mt], bh[nt][0], bh[nt][1]);
            } else {
                uint32_t ah[4][4], al[4][4], bh[4][2], bl[4][2];
#pragma unroll
                for (int mt = 0; mt < 4; ++mt)
#pragma unroll
                    for (int q = 0; q < 4; ++q) {
                        const uint32_t h = f2tf(af[mt][q]);
                        ah[mt][q] = h;
                        al[mt][q] = f2tf(af[mt][q] - __uint_as_float(h));
                    }
#pragma unroll
                for (int nt = 0; nt < 4; ++nt)
#pragma unroll
                    for (int q = 0; q < 2; ++q) {
                        const uint32_t h = f2tf(bf[nt][q]);
                        bh[nt][q] = h;
                        bl[nt][q] = f2tf(bf[nt][q] - __uint_as_float(h));
                    }
#pragma unroll
                for (int mt = 0; mt < 4; ++mt)
#pragma unroll
                    for (int nt = 0; nt < 4; ++nt) {
                        mma_tf32(acc[mt][nt], al[mt], bh[nt][0], bh[nt][1]);
                        mma_tf32(acc[mt][nt], ah[mt], bl[nt][0], bl[nt][1]);
                        mma_tf32(acc[mt][nt], ah[mt], bh[nt][0], bh[nt][1]);
                    }
            }
        }
        ISSUE(kt + 2);
    }
#undef ISSUE

#pragma unroll
    for (int mt = 0; mt < 4; ++mt) {
#pragma unroll
        for (int half = 0; half < 2; ++half) {
            const long row = bm + wm + mt * 16 + gid + half * 8;
#pragma unroll
            for (int nt = 0; nt < 4; ++nt) {
                const int col = bn + wn + nt * 8 + 2 * tig;
                float v0 = acc[mt][nt][half * 2 + 0];
                float v1 = acc[mt][nt][half * 2 + 1];
                if (EPI == 1 || EPI == 3) {
                    v0 += bias[col];
                    v1 += bias[col + 1];
                }
                if (EPI == 3) {
                    const float2 rr = *(const float2*)&R[row * ldr + col];
                    v0 += rr.x; v1 += rr.y;
                }
                if (EPI == 2) {
                    const float2 av = *(const float2*)&A[row * (size_t)lda + col];
                    v0 = av.x * (1.f / (1.f + __expf(-v0)));
                    v1 = av.y * (1.f / (1.f + __expf(-v1)));
                }
                float2 o; o.x = v0; o.y = v1;
                *(float2*)&C[row * (size_t)ldc + col] = o;
            }
        }
    }
}

// =====================================================================
// Generic 32x32 tiled transpose: out[c*R + r] = in[r*C + c]
// =====================================================================
__global__ void transpose_kernel(const float* __restrict__ in, float* __restrict__ out,
                                 int Rr, int Cc)
{
    __shared__ float t[32][33];
    const int c0 = blockIdx.x * 32;
    const int r0 = blockIdx.y * 32;
#pragma unroll
    for (int i = 0; i < 32; i += 8)
        t[threadIdx.y + i][threadIdx.x] =
            in[(size_t)(r0 + threadIdx.y + i) * Cc + c0 + threadIdx.x];
    __syncthreads();
#pragma unroll
    for (int i = 0; i < 32; i += 8)
        out[(size_t)(c0 + threadIdx.y + i) * Rr + r0 + threadIdx.x] =
            t[threadIdx.x][threadIdx.y + i];
}

// =====================================================================
// Row softmax over [B*S, S] with diagonal mask
// =====================================================================
__global__ void softmax_kernel(float* __restrict__ s)
{
    const long row = blockIdx.x;
    const int i = (int)(row & (SS - 1));
    float* p = s + row * SS;
    const int tid = threadIdx.x;

    float vals[8];
    float mx = -1e30f;
#pragma unroll
    for (int u = 0; u < 8; ++u) {
        const int j = tid + u * 256;
        float v = p[j];
        if (j == i) v = -INFINITY;
        vals[u] = v;
        mx = fmaxf(mx, v);
    }
    __shared__ float red[256];
    red[tid] = mx;
    __syncthreads();
#pragma unroll
    for (int st = 128; st; st >>= 1) {
        if (tid < st) red[tid] = fmaxf(red[tid], red[tid + st]);
        __syncthreads();
    }
    mx = red[0];
    __syncthreads();

    float sum = 0.f;
#pragma unroll
    for (int u = 0; u < 8; ++u) {
        vals[u] = __expf(vals[u] - mx);
        sum += vals[u];
    }
    red[tid] = sum;
    __syncthreads();
#pragma unroll
    for (int st = 128; st; st >>= 1) {
        if (tid < st) red[tid] += red[tid + st];
        __syncthreads();
    }
    const float inv = 1.f / red[0];
#pragma unroll
    for (int u = 0; u < 8; ++u) p[tid + u * 256] = vals[u] * inv;
}

__global__ void copy_x_kernel(const float* __restrict__ x, float* __restrict__ rinraw)
{
    const long i = (long)blockIdx.x * 256 + threadIdx.x;
    const long row = i >> 7;
    const long col = i & 127;
    ((float4*)rinraw)[row * (2 * DD / 4) + col] = ((const float4*)x)[i];
}

__global__ void init_kernel()
{
    const int t = blockIdx.x * 256 + threadIdx.x;
    unsigned long long* h = &g_h2[0][0][0];
    if (t < 2 * 2 * HH * BB) h[t] = 0ULL;   // h=0, tag=0
}

// =====================================================================
// Persistent bidirectional GRU v10: self-validating data atoms.
//  - h published as {tag=step+1, h_bits} u64 via st.relaxed.gpu.b64
//    immediately when each gate thread finishes (no fence, no named
//    barrier, no flags). 64-bit relaxed ops are single-copy atomic.
//  - consumer polls element 0 of its 16-atom quarter, then loads the
//    other 15 in parallel with per-element staleness retry: ONE L2
//    round-trip delivers readiness + data.
//  - tensor-core recurrence dot / prefetch-2 / roles unchanged (R14).
// =====================================================================
#define CPB 64
#define HP 516   // padded smem row stride

__device__ __forceinline__ float fsig(float x)  { return 1.f / (1.f + __expf(-x)); }
__device__ __forceinline__ float ftanh(float x) { return 1.f - 2.f / (__expf(2.f * x) + 1.f); }

__global__ void __launch_bounds__(256, 1)
gru_kernel(const float* __restrict__ xwT_f, const float* __restrict__ xwT_b,
           const float* __restrict__ Whh_f, const float* __restrict__ Whh_b,
           const float* __restrict__ bhh_f, const float* __restrict__ bhh_b,
           float* __restrict__ hcatT)
{
    const int cta = blockIdx.x;
    const int dir = cta >> 6;
    const int slice = cta & 63;
    const float* xwT = dir ? xwT_b : xwT_f;
    const float* Whh = dir ? Whh_b : Whh_f;
    const float* bhh = dir ? bhh_b : bhh_f;

    const int tid = threadIdx.x;
    const int w = tid >> 5;
    const int lane = tid & 31;
    const int gid = lane >> 2;
    const int tig = lane & 3;

    __shared__ float smem_s[8 * HP + 8 * 192];   // h_s [8][HP] + red [8 warps][192]
    float* h_s = smem_s;
    float* red = smem_s + 8 * HP;

    // ---- B-fragments (weights), converted once. warp w: k in [64w, 64w+64) ----
    uint32_t bfr[3][8][2];
#pragma unroll
    for (int g = 0; g < 3; ++g)
#pragma unroll
        for (int kt = 0; kt < 8; ++kt) {
            const float* row = Whh + (size_t)(g * HH + slice * 8 + gid) * HH + w * 64 + kt * 8;
            bfr[g][kt][0] = f2tf(__ldg(row + tig));
            bfr[g][kt][1] = f2tf(__ldg(row + tig + 4));
        }

    // ---- gate-thread setup: t2 = b*8 + jl (threads 0..63) ----
    const int t2 = tid;
    const int gb = t2 >> 3;
    const int gjl = t2 & 7;
    const int gj = slice * 8 + gjl;
    float br = 0.f, bz = 0.f, bnb = 0.f;
    const float *pr = nullptr, *pz = nullptr, *pn = nullptr;
    float* hout_base = nullptr;
    if (t2 < 64) {
        br = bhh[gj]; bz = bhh[HH + gj]; bnb = bhh[2 * HH + gj];
        pr = xwT + (size_t)gj * (BB * SS) + gb * SS;
        pz = xwT + (size_t)(HH + gj) * (BB * SS) + gb * SS;
        pn = xwT + (size_t)(2 * HH + gj) * (BB * SS) + gb * SS;
        hout_base = hcatT + (size_t)(dir * HH + gj) * (BB * SS) + gb * SS;
    }

    const int cp_p = tid >> 2;
    const int cp_j0 = cp_p * 8 + (tid & 3) * 2;     // 2 consecutive j rows -> 16 atoms

    // prefetch xw for steps 0,1 (parity regs)
    float xr_e = 0.f, xz_e = 0.f, xn_e = 0.f;
    float xr_o = 0.f, xz_o = 0.f, xn_o = 0.f;
    if (t2 < 64) {
        const int t0 = dir ? (SS - 1) : 0;
        const int t1 = dir ? (SS - 2) : 1;
        xr_e = __ldg(pr + t0); xz_e = __ldg(pz + t0); xn_e = __ldg(pn + t0);
        xr_o = __ldg(pr + t1); xz_o = __ldg(pz + t1); xn_o = __ldg(pn + t1);
    }

    for (int step = 0; step < SS; ++step) {
        const int p = step & 1;
        const int tt = dir ? (SS - 1 - step) : step;

        // ---- A: poll + load self-validating quarter (16 u64 atoms) ----
        {
            const unsigned tag = (unsigned)step;
            const unsigned long long* src = &g_h2[p][dir][(size_t)cp_j0 * 8];
            unsigned long long v[16];
            do { v[0] = ldrel64(src); } while ((unsigned)(v[0] >> 32) != tag);
#pragma unroll
            for (int i = 1; i < 16; ++i) v[i] = ldrel64(src + i);
            bool ok;
            do {
                ok = true;
#pragma unroll
                for (int i = 1; i < 16; ++i)
                    if ((unsigned)(v[i] >> 32) != tag) { v[i] = ldrel64(src + i); ok = false; }
            } while (!ok);
#pragma unroll
            for (int i = 0; i < 16; ++i) {
                const int jj = cp_j0 + (i >> 3);
                const int b = i & 7;
                h_s[b * HP + jj] = __uint_as_float((unsigned)v[i]);
            }
        }
        __syncthreads();   // h_s complete

        // ---- C: tensor-core partial dots (all 8 warps) ----
        float acc[3][4];
#pragma unroll
        for (int g = 0; g < 3; ++g)
#pragma unroll
            for (int q = 0; q < 4; ++q) acc[g][q] = 0.f;

#pragma unroll
        for (int kt = 0; kt < 8; ++kt) {
            const int k0 = w * 64 + kt * 8;
            uint32_t a[4];
            a[0] = f2tf(h_s[gid * HP + k0 + tig]);
            a[2] = f2tf(h_s[gid * HP + k0 + tig + 4]);
            a[1] = 0u;
            a[3] = 0u;
#pragma unroll
            for (int g = 0; g < 3; ++g)
                mma_tf32(acc[g], a, bfr[g][kt][0], bfr[g][kt][1]);
        }
#pragma unroll
        for (int g = 0; g < 3; ++g)
            *(float2*)&red[w * 192 + g * 64 + gid * 8 + 2 * tig] =
                make_float2(acc[g][0], acc[g][1]);

        float hprev = 0.f;
        if (t2 < 64) hprev = h_s[gb * HP + gj];
        __syncthreads();   // red complete

        // ---- E: gate threads reduce + gates + immediate atom publish ----
        if (t2 < 64) {
            float gr = 0.f, gz = 0.f, gn = 0.f;
#pragma unroll
            for (int w2 = 0; w2 < 8; ++w2) {
                gr += red[w2 * 192 + t2];
                gz += red[w2 * 192 + 64 + t2];
                gn += red[w2 * 192 + 128 + t2];
            }
            const float xr_s = p ? xr_o : xr_e;
            const float xz_s = p ? xz_o : xz_e;
            const float xn_s = p ? xn_o : xn_e;
            const float r = fsig(xr_s + gr + br);
            const float z = fsig(xz_s + gz + bz);
            const float n = ftanh(xn_s + r * (gn + bnb));
            const float hn = (1.f - z) * n + z * hprev;

            const unsigned long long pk =
                ((unsigned long long)(unsigned)(step + 1) << 32) |
                (unsigned long long)__float_as_uint(hn);
            strel64(&g_h2[p ^ 1][dir][(size_t)gj * 8 + gb], pk);

            // off critical path: hcatT store + prefetch for step+2
            hout_base[tt] = hn;
            if (step + 2 < SS) {
                const int tn_ = dir ? (SS - 3 - step) : (step + 2);
                if (p) {
                    xr_o = __ldg(pr + tn_); xz_o = __ldg(pz + tn_); xn_o = __ldg(pn + tn_);
                } else {
                    xr_e = __ldg(pr + tn_); xz_e = __ldg(pz + tn_); xn_e = __ldg(pn + tn_);
                }
            }
        }
        // warps 2-7 fall through to next step's poll immediately
    }
}

// =====================================================================
extern "C" void kernel_launch(void* const* d_in, const int* in_sizes, int n_in,
                              void* d_out, int out_size)
{
    (void)in_sizes; (void)n_in; (void)out_size;
    const float* x     = (const float*)d_in[0];
    const float* W     = (const float*)d_in[1];
    const float* Wg    = (const float*)d_in[2];
    const float* Wih_f = (const float*)d_in[3];
    const float* Whh_f = (const float*)d_in[4];
    const float* bih_f = (const float*)d_in[5];
    const float* bhh_f = (const float*)d_in[6];
    const float* Wih_b = (const float*)d_in[7];
    const float* Whh_b = (const float*)d_in[8];
    const float* bih_b = (const float*)d_in[9];
    const float* bhh_b = (const float*)d_in[10];
    const float* Wp    = (const float*)d_in[11];
    const float* bp    = (const float*)d_in[12];
    float* out = (float*)d_out;

    float *Wx, *sc, *rinraw, *rin, *xwf, *xwb, *xwfT, *xwbT, *hcat, *hcatT;
    cudaGetSymbolAddress((void**)&Wx,     g_Wx);
    cudaGetSymbolAddress((void**)&sc,     g_sc);
    cudaGetSymbolAddress((void**)&rinraw, g_rinraw);
    cudaGetSymbolAddress((void**)&rin,    g_rin);
    cudaGetSymbolAddress((void**)&xwf,    g_xwf);
    cudaGetSymbolAddress((void**)&xwb,    g_xwb);
    cudaGetSymbolAddress((void**)&xwfT,   g_xwfT);
    cudaGetSymbolAddress((void**)&xwbT,   g_xwbT);
    cudaGetSymbolAddress((void**)&hcat,   g_hcat);
    cudaGetSymbolAddress((void**)&hcatT,  g_hcatT);

    const int M = BB * SS;
    const int SMEM = 98304;   // 3 stages x 32KB

    cudaFuncSetAttribute(pip_gemm<0, 1, 0>, cudaFuncAttributeMaxDynamicSharedMemorySize, SMEM);
    cudaFuncSetAttribute(pip_gemm<1, 0, 0>, cudaFuncAttributeMaxDynamicSharedMemorySize, SMEM);
    cudaFuncSetAttribute(pip_gemm<0, 0, 1>, cudaFuncAttributeMaxDynamicSharedMemorySize, SMEM);
    cudaFuncSetAttribute(pip_gemm<0, 0, 2>, cudaFuncAttributeMaxDynamicSharedMemorySize, SMEM);
    cudaFuncSetAttribute(pip_gemm<0, 0, 3>, cudaFuncAttributeMaxDynamicSharedMemorySize, SMEM);

    init_kernel<<<64, 256>>>();

    copy_x_kernel<<<(M * DD / 4) / 256, 256>>>(x, rinraw);

    // Wx = x @ W^T (split-tf32: feeds softmax logits)
    pip_gemm<0, 1, 0><<<dim3(DD / 128, M / 128, 1), 256, SMEM>>>(
        x, W, Wx, M, DD, DD, DD, DD, DD, 0, 0, 0, nullptr, nullptr, 0);

    // s[b] = Wx[b] @ x[b]^T (split-tf32 logits)
    pip_gemm<0, 1, 0><<<dim3(SS / 128, SS / 128, BB), 256, SMEM>>>(
        Wx, x, sc, SS, SS, DD, DD, DD, SS,
        (long)SS * DD, (long)SS * DD, (long)SS * SS, nullptr, nullptr, 0);

    softmax_kernel<<<M, 256>>>(sc);

    // rin_raw[:, 512:] = a[b] @ x[b]   (tf32, BMODE1)
    pip_gemm<1, 0, 0><<<dim3(DD / 128, SS / 128, BB), 256, SMEM>>>(
        sc, x, rinraw + DD, SS, DD, SS, SS, DD, 2 * DD,
        (long)SS * SS, (long)SS * DD, (long)SS * 2 * DD, nullptr, nullptr, 0);

    // rin = rin_raw * sigmoid(rin_raw @ Wg^T)
    pip_gemm<0, 0, 2><<<dim3(2 * DD / 128, M / 128, 1), 256, SMEM>>>(
        rinraw, Wg, rin, M, 2 * DD, 2 * DD, 2 * DD, 2 * DD, 2 * DD,
        0, 0, 0, nullptr, nullptr, 0);

    // xw = rin @ Wih^T + bih (both directions)
    pip_gemm<0, 0, 1><<<dim3(3 * HH / 128, M / 128, 1), 256, SMEM>>>(
        rin, Wih_f, xwf, M, 3 * HH, 2 * DD, 2 * DD, 2 * DD, 3 * HH,
        0, 0, 0, bih_f, nullptr, 0);
    pip_gemm<0, 0, 1><<<dim3(3 * HH / 128, M / 128, 1), 256, SMEM>>>(
        rin, Wih_b, xwb, M, 3 * HH, 2 * DD, 2 * DD, 2 * DD, 3 * HH,
        0, 0, 0, bih_b, nullptr, 0);

    // transpose xw to [g*H+j][b*S+t] for streaming GRU loads
    transpose_kernel<<<dim3(3 * HH / 32, M / 32), dim3(32, 8)>>>(xwf, xwfT, M, 3 * HH);
    transpose_kernel<<<dim3(3 * HH / 32, M / 32), dim3(32, 8)>>>(xwb, xwbT, M, 3 * HH);

    // bidirectional GRU -> hcatT [2H][M]
    gru_kernel<<<128, 256>>>(xwfT, xwbT, Whh_f, Whh_b, bhh_f, bhh_b, hcatT);

    // transpose hcatT -> hcat [M][2H]
    transpose_kernel<<<dim3(M / 32, 2 * HH / 32), dim3(32, 8)>>>(hcatT, hcat, 2 * HH, M);

    // out = x + hcat @ Wp^T + bp
    pip_gemm<0, 0, 3><<<dim3(DD / 128, M / 128, 1), 256, SMEM>>>(
        hcat, Wp, out, M, DD, 2 * HH, 2 * HH, 2 * HH, DD,
        0, 0, 0, bp, x, DD);
}

// round 16
// speedup vs baseline: 1.5772x; 1.5772x over previous
#include <cuda_runtime.h>
#include <cstdint>

#define BB 8
#define SS 2048
#define DD 512
#define HH 512

// ---------------- scratch (device globals; no cudaMalloc allowed) ----------------
__device__ float g_Wx[(size_t)BB * SS * DD];          //  32 MB
__device__ float g_sc[(size_t)BB * SS * SS];          // 134 MB
__device__ float g_rinraw[(size_t)BB * SS * 2 * DD];  //  64 MB
__device__ float g_rin[(size_t)BB * SS * 2 * DD];     //  64 MB
__device__ float g_xwf[(size_t)BB * SS * 3 * HH];     //  96 MB
__device__ float g_xwb[(size_t)BB * SS * 3 * HH];     //  96 MB
__device__ float g_xwfT[(size_t)3 * HH * BB * SS];    //  96 MB (transposed [g*H+j][b*S+t])
__device__ float g_xwbT[(size_t)3 * HH * BB * SS];    //  96 MB
__device__ float g_hcat[(size_t)BB * SS * 2 * HH];    //  64 MB
__device__ float g_hcatT[(size_t)2 * HH * BB * SS];   //  64 MB (transposed)
__device__ float g_hT[2][2][HH * BB];                 // h state, [phase][dir][j*8+b]
__device__ unsigned g_flag[2][64][32];                // per-CTA publish flags (128B apart)

// =====================================================================
// tf32 helpers
// =====================================================================
__device__ __forceinline__ uint32_t f2tf(float f) {
    uint32_t u; asm("cvt.rna.tf32.f32 %0, %1;" : "=r"(u) : "f"(f)); return u;
}
__device__ __forceinline__ void mma_tf32(float* c, const uint32_t* a, uint32_t b0, uint32_t b1) {
    asm volatile(
        "mma.sync.aligned.m16n8k8.row.col.f32.tf32.tf32.f32 "
        "{%0,%1,%2,%3}, {%4,%5,%6,%7}, {%8,%9}, {%0,%1,%2,%3};\n"
        : "+f"(c[0]), "+f"(c[1]), "+f"(c[2]), "+f"(c[3])
        : "r"(a[0]), "r"(a[1]), "r"(a[2]), "r"(a[3]), "r"(b0), "r"(b1));
}
__device__ __forceinline__ uint32_t smem_u32(const void* p) {
    uint32_t a;
    asm("{ .reg .u64 t; cvta.to.shared.u64 t, %1; cvt.u32.u64 %0, t; }" : "=r"(a) : "l"(p));
    return a;
}
#define CP_ASYNC16(dst, src) \
    asm volatile("cp.async.cg.shared.global [%0], [%1], 16;" :: "r"(dst), "l"(src))
#define CP_COMMIT() asm volatile("cp.async.commit_group;" ::: "memory")
#define CP_WAIT1()  asm volatile("cp.async.wait_group 1;" ::: "memory")

// =====================================================================
// tf32 mma.sync GEMM with 3-stage cp.async pipeline (unchanged from R5/R7).
// =====================================================================
template <int BMODE, int SPLIT, int EPI>
__global__ void
__launch_bounds__(256, SPLIT ? 1 : 2)
pip_gemm(const float* __restrict__ A, const float* __restrict__ B,
         float* __restrict__ C, int M, int N, int K,
         int lda, int ldb, int ldc,
         long sA, long sB, long sC,
         const float* __restrict__ bias,
         const float* __restrict__ R, int ldr)
{
    A += (long)blockIdx.z * sA;
    B += (long)blockIdx.z * sB;
    C += (long)blockIdx.z * sC;

    extern __shared__ float sm[];
    const uint32_t sbase = smem_u32(sm);

    const int tid  = threadIdx.x;
    const int lane = tid & 31;
    const int warp = tid >> 5;
    const int gid  = lane >> 2;
    const int tig  = lane & 3;
    const int wm   = (warp >> 2) * 64;
    const int wn   = (warp & 3) * 32;
    const int bm   = blockIdx.y * 128;
    const int bn   = blockIdx.x * 128;
    const int nk   = K >> 5;

    float acc[4][4][4];
#pragma unroll
    for (int mt = 0; mt < 4; ++mt)
#pragma unroll
        for (int nt = 0; nt < 4; ++nt)
#pragma unroll
            for (int q = 0; q < 4; ++q) acc[mt][nt][q] = 0.f;

    int b1off0[4], b1off1[4];
    if (BMODE == 1) {
#pragma unroll
        for (int nt = 0; nt < 4; ++nt) {
            const int n = wn + nt * 8 + gid;
            b1off0[nt] = tig * 128       + ((((n >> 2) ^ (tig << 2)) << 2) + (n & 3));
            b1off1[nt] = (tig + 4) * 128 + ((((n >> 2) ^ ((tig + 4) << 2)) << 2) + (n & 3));
        }
    }

    const int arow = tid >> 3, ac4 = tid & 7;

#define ISSUE(kt)                                                             \
    {                                                                         \
        if ((kt) < nk) {                                                      \
            const uint32_t sa = sbase + ((kt) % 3) * 32768;                   \
            const uint32_t sb = sa + 16384;                                   \
            _Pragma("unroll")                                                 \
            for (int i = 0; i < 4; ++i) {                                     \
                const int row = arow + 32 * i;                                \
                const uint32_t dst = sa + (uint32_t)(row * 32 + ((ac4 ^ (row & 7)) << 2)) * 4; \
                CP_ASYNC16(dst, A + (size_t)(bm + row) * lda + (kt) * 32 + ac4 * 4); \
            }                                                                 \
            if (BMODE == 0) {                                                 \
                _Pragma("unroll")                                             \
                for (int i = 0; i < 4; ++i) {                                 \
                    const int row = arow + 32 * i;                            \
                    const uint32_t dst = sb + (uint32_t)(row * 32 + ((ac4 ^ (row & 7)) << 2)) * 4; \
                    CP_ASYNC16(dst, B + (size_t)(bn + row) * ldb + (kt) * 32 + ac4 * 4); \
                }                                                             \
            } else {                                                          \
                _Pragma("unroll")                                             \
                for (int i = 0; i < 4; ++i) {                                 \
                    const int idx = tid + 256 * i;                            \
                    const int row = idx >> 5, c4 = idx & 31;                  \
                    const uint32_t dst = sb + (uint32_t)(row * 128 + ((c4 ^ ((row & 7) << 2)) << 2)) * 4; \
                    CP_ASYNC16(dst, B + (size_t)((kt) * 32 + row) * ldb + bn + c4 * 4); \
                }                                                             \
            }                                                                 \
        }                                                                     \
        CP_COMMIT();                                                          \
    }

    ISSUE(0);
    ISSUE(1);

    for (int kt = 0; kt < nk; ++kt) {
        CP_WAIT1();
        __syncthreads();

        const float* pa = sm + (kt % 3) * 8192;
        const float* pb = pa + 4096;

#pragma unroll
        for (int ks = 0; ks < 4; ++ks) {
            const int s0 = tig + (((2 * ks)     ^ gid) << 2);
            const int s1 = tig + (((2 * ks + 1) ^ gid) << 2);

            float af[4][4];
#pragma unroll
            for (int mt = 0; mt < 4; ++mt) {
                const int r0 = (wm + mt * 16 + gid) * 32;
                const int r1 = r0 + 256;
                af[mt][0] = pa[r0 + s0];
                af[mt][1] = pa[r1 + s0];
                af[mt][2] = pa[r0 + s1];
                af[mt][3] = pa[r1 + s1];
            }
            float bf[4][2];
#pragma unroll
            for (int nt = 0; nt < 4; ++nt) {
                if (BMODE == 0) {
                    const int nrow = (wn + nt * 8 + gid) * 32;
                    bf[nt][0] = pb[nrow + s0];
                    bf[nt][1] = pb[nrow + s1];
                } else {
                    bf[nt][0] = pb[b1off0[nt] + ks * 1024];
                    bf[nt][1] = pb[b1off1[nt] + ks * 1024];
                }
            }

            if (!SPLIT) {
                uint32_t ah[4][4], bh[4][2];
#pragma unroll
                for (int mt = 0; mt < 4; ++mt)
#pragma unroll
                    for (int q = 0; q < 4; ++q) ah[mt][q] = f2tf(af[mt][q]);
#pragma unroll
                for (int nt = 0; nt < 4; ++nt) {
                    bh[nt][0] = f2tf(bf[nt][0]);
                    bh[nt][1] = f2tf(bf[nt][1]);
                }
#pragma unroll
                for (int mt = 0; mt < 4; ++mt)
#pragma unroll
                    for (int nt = 0; nt < 4; ++nt)
                        mma_tf32(acc[mt][nt], ah[mt], bh[nt][0], bh[nt][1]);
            } else {
                uint32_t ah[4][4], al[4][4], bh[4][2], bl[4][2];
#pragma unroll
                for (int mt = 0; mt < 4; ++mt)
#pragma unroll
                    for (int q = 0; q < 4; ++q) {
                        const uint32_t h = f2tf(af[mt][q]);
                        ah[mt][q] = h;
                        al[mt][q] = f2tf(af[mt][q] - __uint_as_float(h));
                    }
#pragma unroll
                for (int nt = 0; nt < 4; ++nt)
#pragma unroll
                    for (int q = 0; q < 2; ++q) {
                        const uint32_t h = f2tf(bf[nt][q]);
                        bh[nt][q] = h;
                        bl[nt][q] = f2tf(bf[nt][q] - __uint_as_float(h));
                    }
#pragma unroll
                for (int mt = 0; mt < 4; ++mt)
#pragma unroll
                    for (int nt = 0; nt < 4; ++nt) {
                        mma_tf32(acc[mt][nt], al[mt], bh[nt][0], bh[nt][1]);
                        mma_tf32(acc[mt][nt], ah[mt], bl[nt][0], bl[nt][1]);
                        mma_tf32(acc[mt][nt], ah[mt], bh[nt][0], bh[nt][1]);
                    }
            }
        }
        ISSUE(kt + 2);
    }
#undef ISSUE

#pragma unroll
    for (int mt = 0; mt < 4; ++mt) {
#pragma unroll
        for (int half = 0; half < 2; ++half) {
            const long row = bm + wm + mt * 16 + gid + half * 8;
#pragma unroll
            for (int nt = 0; nt < 4; ++nt) {
                const int col = bn + wn + nt * 8 + 2 * tig;
                float v0 = acc[mt][nt][half * 2 + 0];
                float v1 = acc[mt][nt][half * 2 + 1];
                if (EPI == 1 || EPI == 3) {
                    v0 += bias[col];
                    v1 += bias[col + 1];
                }
                if (EPI == 3) {
                    const float2 rr = *(const float2*)&R[row * ldr + col];
                    v0 += rr.x; v1 += rr.y;
                }
                if (EPI == 2) {
                    const float2 av = *(const float2*)&A[row * (size_t)lda + col];
                    v0 = av.x * (1.f / (1.f + __expf(-v0)));
                    v1 = av.y * (1.f / (1.f + __expf(-v1)));
                }
                float2 o; o.x = v0; o.y = v1;
                *(float2*)&C[row * (size_t)ldc + col] = o;
            }
        }
    }
}

// =====================================================================
// Generic 32x32 tiled transpose: out[c*R + r] = in[r*C + c]
// =====================================================================
__global__ void transpose_kernel(const float* __restrict__ in, float* __restrict__ out,
                                 int Rr, int Cc)
{
    __shared__ float t[32][33];
    const int c0 = blockIdx.x * 32;
    const int r0 = blockIdx.y * 32;
#pragma unroll
    for (int i = 0; i < 32; i += 8)
        t[threadIdx.y + i][threadIdx.x] =
            in[(size_t)(r0 + threadIdx.y + i) * Cc + c0 + threadIdx.x];
    __syncthreads();
#pragma unroll
    for (int i = 0; i < 32; i += 8)
        out[(size_t)(c0 + threadIdx.y + i) * Rr + r0 + threadIdx.x] =
            t[threadIdx.x][threadIdx.y + i];
}

// =====================================================================
// Row softmax over [B*S, S] with diagonal mask
// =====================================================================
__global__ void softmax_kernel(float* __restrict__ s)
{
    const long row = blockIdx.x;
    const int i = (int)(row & (SS - 1));
    float* p = s + row * SS;
    const int tid = threadIdx.x;

    float vals[8];
    float mx = -1e30f;
#pragma unroll
    for (int u = 0; u < 8; ++u) {
        const int j = tid + u * 256;
        float v = p[j];
        if (j == i) v = -INFINITY;
        vals[u] = v;
        mx = fmaxf(mx, v);
    }
    __shared__ float red[256];
    red[tid] = mx;
    __syncthreads();
#pragma unroll
    for (int st = 128; st; st >>= 1) {
        if (tid < st) red[tid] = fmaxf(red[tid], red[tid + st]);
        __syncthreads();
    }
    mx = red[0];
    __syncthreads();

    float sum = 0.f;
#pragma unroll
    for (int u = 0; u < 8; ++u) {
        vals[u] = __expf(vals[u] - mx);
        sum += vals[u];
    }
    red[tid] = sum;
    __syncthreads();
#pragma unroll
    for (int st = 128; st; st >>= 1) {
        if (tid < st) red[tid] += red[tid + st];
        __syncthreads();
    }
    const float inv = 1.f / red[0];
#pragma unroll
    for (int u = 0; u < 8; ++u) p[tid + u * 256] = vals[u] * inv;
}

__global__ void copy_x_kernel(const float* __restrict__ x, float* __restrict__ rinraw)
{
    const long i = (long)blockIdx.x * 256 + threadIdx.x;
    const long row = i >> 7;
    const long col = i & 127;
    ((float4*)rinraw)[row * (2 * DD / 4) + col] = ((const float4*)x)[i];
}

__global__ void init_kernel()
{
    const int t = blockIdx.x * 256 + threadIdx.x;
    float* h = &g_hT[0][0][0];
    if (t < 2 * 2 * HH * BB) h[t] = 0.f;
    unsigned* fl = &g_flag[0][0][0];
    if (t < 2 * 64 * 32) fl[t] = 0u;
}

// =====================================================================
// Persistent bidirectional GRU v9r (R14 revert + float2 STS in copy):
//  - tensor-core recurrence dot (m16n8k8 tf32), weights in frags
//  - per-producer poll+copy streaming exchange, single-writer flags
//  - xw prefetch distance 2 (parity register sets)
// =====================================================================
#define CPB 64
#define HP 516   // padded smem row stride

__device__ __forceinline__ float fsig(float x)  { return 1.f / (1.f + __expf(-x)); }
__device__ __forceinline__ float ftanh(float x) { return 1.f - 2.f / (__expf(2.f * x) + 1.f); }

__global__ void __launch_bounds__(256, 1)
gru_kernel(const float* __restrict__ xwT_f, const float* __restrict__ xwT_b,
           const float* __restrict__ Whh_f, const float* __restrict__ Whh_b,
           const float* __restrict__ bhh_f, const float* __restrict__ bhh_b,
           float* __restrict__ hcatT)
{
    const int cta = blockIdx.x;
    const int dir = cta >> 6;
    const int slice = cta & 63;
    const float* xwT = dir ? xwT_b : xwT_f;
    const float* Whh = dir ? Whh_b : Whh_f;
    const float* bhh = dir ? bhh_b : bhh_f;

    const int tid = threadIdx.x;
    const int w = tid >> 5;
    const int lane = tid & 31;
    const int gid = lane >> 2;      // fragment row / n-index
    const int tig = lane & 3;       // fragment k-index

    __shared__ float smem_s[8 * HP + 8 * 192];   // h_s [8][HP] + red [8 warps][192]
    float* h_s = smem_s;
    float* red = smem_s + 8 * HP;

    // ---- B-fragments (weights), converted once. warp w: k in [64w, 64w+64) ----
    uint32_t bfr[3][8][2];
#pragma unroll
    for (int g = 0; g < 3; ++g)
#pragma unroll
        for (int kt = 0; kt < 8; ++kt) {
            const float* row = Whh + (size_t)(g * HH + slice * 8 + gid) * HH + w * 64 + kt * 8;
            bfr[g][kt][0] = f2tf(__ldg(row + tig));
            bfr[g][kt][1] = f2tf(__ldg(row + tig + 4));
        }

    // ---- gate-thread setup: t2 = b*8 + jl (threads 0..63) ----
    const int t2 = tid;
    const int gb = t2 >> 3;
    const int gjl = t2 & 7;
    const int gj = slice * 8 + gjl;
    float br = 0.f, bz = 0.f, bnb = 0.f;
    const float *pr = nullptr, *pz = nullptr, *pn = nullptr;
    float* hout_base = nullptr;
    if (t2 < 64) {
        br = bhh[gj]; bz = bhh[HH + gj]; bnb = bhh[2 * HH + gj];
        pr = xwT + (size_t)gj * (BB * SS) + gb * SS;
        pz = xwT + (size_t)(HH + gj) * (BB * SS) + gb * SS;
        pn = xwT + (size_t)(2 * HH + gj) * (BB * SS) + gb * SS;
        hout_base = hcatT + (size_t)(dir * HH + gj) * (BB * SS) + gb * SS;
    }

    unsigned* myflag = &g_flag[dir][slice][0];
    const int cp_p = tid >> 2;
    const int cp_j0 = cp_p * 8 + (tid & 3) * 2;
    unsigned* cp_flag = &g_flag[dir][cp_p][0];

    // prefetch xw for steps 0,1 (parity regs)
    float xr_e = 0.f, xz_e = 0.f, xn_e = 0.f;
    float xr_o = 0.f, xz_o = 0.f, xn_o = 0.f;
    if (t2 < 64) {
        const int t0 = dir ? (SS - 1) : 0;
        const int t1 = dir ? (SS - 2) : 1;
        xr_e = __ldg(pr + t0); xz_e = __ldg(pz + t0); xn_e = __ldg(pn + t0);
        xr_o = __ldg(pr + t1); xz_o = __ldg(pz + t1); xn_o = __ldg(pn + t1);
    }

    for (int step = 0; step < SS; ++step) {
        const int p = step & 1;
        const int tt = dir ? (SS - 1 - step) : step;

        // ---- A: poll own producer's flag, copy its 64B quarter into h_s ----
        if (step > 0) {
            const unsigned target = (unsigned)step;
            unsigned v;
            do {
                asm volatile("ld.acquire.gpu.u32 %0, [%1];" : "=r"(v) : "l"(cp_flag));
            } while (v < target);
        }
        {
            const float4* src = (const float4*)(&g_hT[p][dir][0]) + cp_j0 * 2;
            const float4 v0 = __ldcg(src);
            const float4 v1 = __ldcg(src + 1);
            const float4 v2 = __ldcg(src + 2);
            const float4 v3 = __ldcg(src + 3);
            // rows cp_j0 / cp_j0+1 are adjacent in h_s: store float2 pairs
            *(float2*)&h_s[0 * HP + cp_j0] = make_float2(v0.x, v2.x);
            *(float2*)&h_s[1 * HP + cp_j0] = make_float2(v0.y, v2.y);
            *(float2*)&h_s[2 * HP + cp_j0] = make_float2(v0.z, v2.z);
            *(float2*)&h_s[3 * HP + cp_j0] = make_float2(v0.w, v2.w);
            *(float2*)&h_s[4 * HP + cp_j0] = make_float2(v1.x, v3.x);
            *(float2*)&h_s[5 * HP + cp_j0] = make_float2(v1.y, v3.y);
            *(float2*)&h_s[6 * HP + cp_j0] = make_float2(v1.z, v3.z);
            *(float2*)&h_s[7 * HP + cp_j0] = make_float2(v1.w, v3.w);
        }
        __syncthreads();   // h_s complete

        // ---- C: tensor-core partial dots (all 8 warps) ----
        float acc[3][4];
#pragma unroll
        for (int g = 0; g < 3; ++g)
#pragma unroll
            for (int q = 0; q < 4; ++q) acc[g][q] = 0.f;

#pragma unroll
        for (int kt = 0; kt < 8; ++kt) {
            const int k0 = w * 64 + kt * 8;
            uint32_t a[4];
            a[0] = f2tf(h_s[gid * HP + k0 + tig]);
            a[2] = f2tf(h_s[gid * HP + k0 + tig + 4]);
            a[1] = 0u;
            a[3] = 0u;
#pragma unroll
            for (int g = 0; g < 3; ++g)
                mma_tf32(acc[g], a, bfr[g][kt][0], bfr[g][kt][1]);
        }
        // store partials: red[w][g*64 + row(gid)*8 + 2*tig (+1)]
#pragma unroll
        for (int g = 0; g < 3; ++g)
            *(float2*)&red[w * 192 + g * 64 + gid * 8 + 2 * tig] =
                make_float2(acc[g][0], acc[g][1]);

        // hprev for gate threads (read h_s BEFORE sync2 so phase E is h_s-free)
        float hprev = 0.f;
        if (t2 < 64) hprev = h_s[gb * HP + gj];
        __syncthreads();   // red complete

        // ---- E: gate threads (warps 0-1) reduce + gates + publish ----
        if (t2 < 64) {
            float gr = 0.f, gz = 0.f, gn = 0.f;
#pragma unroll
            for (int w2 = 0; w2 < 8; ++w2) {
                gr += red[w2 * 192 + t2];
                gz += red[w2 * 192 + 64 + t2];
                gn += red[w2 * 192 + 128 + t2];
            }
            const float xr_s = p ? xr_o : xr_e;
            const float xz_s = p ? xz_o : xz_e;
            const float xn_s = p ? xn_o : xn_e;
            const float r = fsig(xr_s + gr + br);
            const float z = fsig(xz_s + gz + bz);
            const float n = ftanh(xn_s + r * (gn + bnb));
            const float hn = (1.f - z) * n + z * hprev;
            g_hT[p ^ 1][dir][gj * 8 + gb] = hn;

            asm volatile("bar.sync 1, 64;" ::: "memory");
            if (tid == 0) {
                __threadfence();
                asm volatile("st.relaxed.gpu.u32 [%0], %1;"
                             :: "l"(myflag), "r"((unsigned)(step + 1)) : "memory");
            }

            // off critical path: hcatT store + prefetch for step+2
            hout_base[tt] = hn;
            if (step + 2 < SS) {
                const int tn_ = dir ? (SS - 3 - step) : (step + 2);
                if (p) {
                    xr_o = __ldg(pr + tn_); xz_o = __ldg(pz + tn_); xn_o = __ldg(pn + tn_);
                } else {
                    xr_e = __ldg(pr + tn_); xz_e = __ldg(pz + tn_); xn_e = __ldg(pn + tn_);
                }
            }
        }
        // warps 2-7 fall through to next step's poll+copy immediately
    }
}

// =====================================================================
extern "C" void kernel_launch(void* const* d_in, const int* in_sizes, int n_in,
                              void* d_out, int out_size)
{
    (void)in_sizes; (void)n_in; (void)out_size;
    const float* x     = (const float*)d_in[0];
    const float* W     = (const float*)d_in[1];
    const float* Wg    = (const float*)d_in[2];
    const float* Wih_f = (const float*)d_in[3];
    const float* Whh_f = (const float*)d_in[4];
    const float* bih_f = (const float*)d_in[5];
    const float* bhh_f = (const float*)d_in[6];
    const float* Wih_b = (const float*)d_in[7];
    const float* Whh_b = (const float*)d_in[8];
    const float* bih_b = (const float*)d_in[9];
    const float* bhh_b = (const float*)d_in[10];
    const float* Wp    = (const float*)d_in[11];
    const float* bp    = (const float*)d_in[12];
    float* out = (float*)d_out;

    float *Wx, *sc, *rinraw, *rin, *xwf, *xwb, *xwfT, *xwbT, *hcat, *hcatT;
    cudaGetSymbolAddress((void**)&Wx,     g_Wx);
    cudaGetSymbolAddress((void**)&sc,     g_sc);
    cudaGetSymbolAddress((void**)&rinraw, g_rinraw);
    cudaGetSymbolAddress((void**)&rin,    g_rin);
    cudaGetSymbolAddress((void**)&xwf,    g_xwf);
    cudaGetSymbolAddress((void**)&xwb,    g_xwb);
    cudaGetSymbolAddress((void**)&xwfT,   g_xwfT);
    cudaGetSymbolAddress((void**)&xwbT,   g_xwbT);
    cudaGetSymbolAddress((void**)&hcat,   g_hcat);
    cudaGetSymbolAddress((void**)&hcatT,  g_hcatT);

    const int M = BB * SS;
    const int SMEM = 98304;   // 3 stages x 32KB

    cudaFuncSetAttribute(pip_gemm<0, 1, 0>, cudaFuncAttributeMaxDynamicSharedMemorySize, SMEM);
    cudaFuncSetAttribute(pip_gemm<1, 0, 0>, cudaFuncAttributeMaxDynamicSharedMemorySize, SMEM);
    cudaFuncSetAttribute(pip_gemm<0, 0, 1>, cudaFuncAttributeMaxDynamicSharedMemorySize, SMEM);
    cudaFuncSetAttribute(pip_gemm<0, 0, 2>, cudaFuncAttributeMaxDynamicSharedMemorySize, SMEM);
    cudaFuncSetAttribute(pip_gemm<0, 0, 3>, cudaFuncAttributeMaxDynamicSharedMemorySize, SMEM);

    init_kernel<<<64, 256>>>();

    copy_x_kernel<<<(M * DD / 4) / 256, 256>>>(x, rinraw);

    // Wx = x @ W^T (split-tf32: feeds softmax logits)
    pip_gemm<0, 1, 0><<<dim3(DD / 128, M / 128, 1), 256, SMEM>>>(
        x, W, Wx, M, DD, DD, DD, DD, DD, 0, 0, 0, nullptr, nullptr, 0);

    // s[b] = Wx[b] @ x[b]^T (split-tf32 logits)
    pip_gemm<0, 1, 0><<<dim3(SS / 128, SS / 128, BB), 256, SMEM>>>(
        Wx, x, sc, SS, SS, DD, DD, DD, SS,
        (long)SS * DD, (long)SS * DD, (long)SS * SS, nullptr, nullptr, 0);

    softmax_kernel<<<M, 256>>>(sc);

    // rin_raw[:, 512:] = a[b] @ x[b]   (tf32, BMODE1)
    pip_gemm<1, 0, 0><<<dim3(DD / 128, SS / 128, BB), 256, SMEM>>>(
        sc, x, rinraw + DD, SS, DD, SS, SS, DD, 2 * DD,
        (long)SS * SS, (long)SS * DD, (long)SS * 2 * DD, nullptr, nullptr, 0);

    // rin = rin_raw * sigmoid(rin_raw @ Wg^T)
    pip_gemm<0, 0, 2><<<dim3(2 * DD / 128, M / 128, 1), 256, SMEM>>>(
        rinraw, Wg, rin, M, 2 * DD, 2 * DD, 2 * DD, 2 * DD, 2 * DD,
        0, 0, 0, nullptr, nullptr, 0);

    // xw = rin @ Wih^T + bih (both directions)
    pip_gemm<0, 0, 1><<<dim3(3 * HH / 128, M / 128, 1), 256, SMEM>>>(
        rin, Wih_f, xwf, M, 3 * HH, 2 * DD, 2 * DD, 2 * DD, 3 * HH,
        0, 0, 0, bih_f, nullptr, 0);
    pip_gemm<0, 0, 1><<<dim3(3 * HH / 128, M / 128, 1), 256, SMEM>>>(
        rin, Wih_b, xwb, M, 3 * HH, 2 * DD, 2 * DD, 2 * DD, 3 * HH,
        0, 0, 0, bih_b, nullptr, 0);

    // transpose xw to [g*H+j][b*S+t] for streaming GRU loads
    transpose_kernel<<<dim3(3 * HH / 32, M / 32), dim3(32, 8)>>>(xwf, xwfT, M, 3 * HH);
    transpose_kernel<<<dim3(3 * HH / 32, M / 32), dim3(32, 8)>>>(xwb, xwbT, M, 3 * HH);

    // bidirectional GRU -> hcatT [2H][M]
    gru_kernel<<<128, 256>>>(xwfT, xwbT, Whh_f, Whh_b, bhh_f, bhh_b, hcatT);

    // transpose hcatT -> hcat [M][2H]
    transpose_kernel<<<dim3(M / 32, 2 * HH / 32), dim3(32, 8)>>>(hcatT, hcat, 2 * HH, M);

    // out = x + hcat @ Wp^T + bp
    pip_gemm<0, 0, 3><<<dim3(DD / 128, M / 128, 1), 256, SMEM>>>(
        hcat, Wp, out, M, DD, 2 * HH, 2 * HH, 2 * HH, DD,
        0, 0, 0, bp, x, DD);
}

// round 17
// speedup vs baseline: 1.6243x; 1.0299x over previous
#include <cuda_runtime.h>
#include <cstdint>

#define BB 8
#define SS 2048
#define DD 512
#define HH 512

// ---------------- scratch (device globals; no cudaMalloc allowed) ----------------
__device__ float g_Wx[(size_t)BB * SS * DD];          //  32 MB
__device__ float g_sc[(size_t)BB * SS * SS];          // 134 MB
__device__ float g_rinraw[(size_t)BB * SS * 2 * DD];  //  64 MB
__device__ float g_rin[(size_t)BB * SS * 2 * DD];     //  64 MB
__device__ float g_xwf[(size_t)BB * SS * 3 * HH];     //  96 MB
__device__ float g_xwb[(size_t)BB * SS * 3 * HH];     //  96 MB
__device__ float g_xwfT[(size_t)3 * HH * BB * SS];    //  96 MB (transposed [g*H+j][b*S+t])
__device__ float g_xwbT[(size_t)3 * HH * BB * SS];    //  96 MB
__device__ float g_hcat[(size_t)BB * SS * 2 * HH];    //  64 MB
__device__ float g_hcatT[(size_t)2 * HH * BB * SS];   //  64 MB (transposed)
__device__ float g_hT[2][2][HH * BB];                 // h state, [phase][dir][j*8+b]
__device__ unsigned g_flag[2][64][32];                // per-CTA publish flags (128B apart)
// hi/lo tf32 decompositions for the accuracy-critical score path
__device__ float g_xhi[(size_t)BB * SS * DD];         //  32 MB
__device__ float g_xlo[(size_t)BB * SS * DD];         //  32 MB
__device__ float g_whi[(size_t)DD * DD];              //   1 MB
__device__ float g_wlo[(size_t)DD * DD];              //   1 MB
__device__ float g_wxhi[(size_t)BB * SS * DD];        //  32 MB
__device__ float g_wxlo[(size_t)BB * SS * DD];        //  32 MB

// =====================================================================
// tf32 helpers
// =====================================================================
__device__ __forceinline__ uint32_t f2tf(float f) {
    uint32_t u; asm("cvt.rna.tf32.f32 %0, %1;" : "=r"(u) : "f"(f)); return u;
}
__device__ __forceinline__ void mma_tf32(float* c, const uint32_t* a, uint32_t b0, uint32_t b1) {
    asm volatile(
        "mma.sync.aligned.m16n8k8.row.col.f32.tf32.tf32.f32 "
        "{%0,%1,%2,%3}, {%4,%5,%6,%7}, {%8,%9}, {%0,%1,%2,%3};\n"
        : "+f"(c[0]), "+f"(c[1]), "+f"(c[2]), "+f"(c[3])
        : "r"(a[0]), "r"(a[1]), "r"(a[2]), "r"(a[3]), "r"(b0), "r"(b1));
}
__device__ __forceinline__ uint32_t smem_u32(const void* p) {
    uint32_t a;
    asm("{ .reg .u64 t; cvta.to.shared.u64 t, %1; cvt.u32.u64 %0, t; }" : "=r"(a) : "l"(p));
    return a;
}
#define CP_ASYNC16(dst, src) \
    asm volatile("cp.async.cg.shared.global [%0], [%1], 16;" :: "r"(dst), "l"(src))
#define CP_COMMIT() asm volatile("cp.async.commit_group;" ::: "memory")
#define CP_WAIT1()  asm volatile("cp.async.wait_group 1;" ::: "memory")

// =====================================================================
// tf32 mma.sync GEMM with 3-stage cp.async pipeline (non-split variants).
//   BMODE 0: B [N,K] row-major   BMODE 1: B [K,N] row-major
//   EPI 0 none / 1 +bias / 2 C=A[m,n]*sigmoid(acc) (N==K) / 3 +bias+R
// =====================================================================
template <int BMODE, int EPI>
__global__ void
__launch_bounds__(256, 2)
pip_gemm(const float* __restrict__ A, const float* __restrict__ B,
         float* __restrict__ C, int M, int N, int K,
         int lda, int ldb, int ldc,
         long sA, long sB, long sC,
         const float* __restrict__ bias,
         const float* __restrict__ R, int ldr)
{
    A += (long)blockIdx.z * sA;
    B += (long)blockIdx.z * sB;
    C += (long)blockIdx.z * sC;

    extern __shared__ float sm[];
    const uint32_t sbase = smem_u32(sm);

    const int tid  = threadIdx.x;
    const int lane = tid & 31;
    const int warp = tid >> 5;
    const int gid  = lane >> 2;
    const int tig  = lane & 3;
    const int wm   = (warp >> 2) * 64;
    const int wn   = (warp & 3) * 32;
    const int bm   = blockIdx.y * 128;
    const int bn   = blockIdx.x * 128;
    const int nk   = K >> 5;

    float acc[4][4][4];
#pragma unroll
    for (int mt = 0; mt < 4; ++mt)
#pragma unroll
        for (int nt = 0; nt < 4; ++nt)
#pragma unroll
            for (int q = 0; q < 4; ++q) acc[mt][nt][q] = 0.f;

    int b1off0[4], b1off1[4];
    if (BMODE == 1) {
#pragma unroll
        for (int nt = 0; nt < 4; ++nt) {
            const int n = wn + nt * 8 + gid;
            b1off0[nt] = tig * 128       + ((((n >> 2) ^ (tig << 2)) << 2) + (n & 3));
            b1off1[nt] = (tig + 4) * 128 + ((((n >> 2) ^ ((tig + 4) << 2)) << 2) + (n & 3));
        }
    }

    const int arow = tid >> 3, ac4 = tid & 7;

#define ISSUE(kt)                                                             \
    {                                                                         \
        if ((kt) < nk) {                                                      \
            const uint32_t sa = sbase + ((kt) % 3) * 32768;                   \
            const uint32_t sb = sa + 16384;                                   \
            _Pragma("unroll")                                                 \
            for (int i = 0; i < 4; ++i) {                                     \
                const int row = arow + 32 * i;                                \
                const uint32_t dst = sa + (uint32_t)(row * 32 + ((ac4 ^ (row & 7)) << 2)) * 4; \
                CP_ASYNC16(dst, A + (size_t)(bm + row) * lda + (kt) * 32 + ac4 * 4); \
            }                                                                 \
            if (BMODE == 0) {                                                 \
                _Pragma("unroll")                                             \
                for (int i = 0; i < 4; ++i) {                                 \
                    const int row = arow + 32 * i;                            \
                    const uint32_t dst = sb + (uint32_t)(row * 32 + ((ac4 ^ (row & 7)) << 2)) * 4; \
                    CP_ASYNC16(dst, B + (size_t)(bn + row) * ldb + (kt) * 32 + ac4 * 4); \
                }                                                             \
            } else {                                                          \
                _Pragma("unroll")                                             \
                for (int i = 0; i < 4; ++i) {                                 \
                    const int idx = tid + 256 * i;                            \
                    const int row = idx >> 5, c4 = idx & 31;                  \
                    const uint32_t dst = sb + (uint32_t)(row * 128 + ((c4 ^ ((row & 7) << 2)) << 2)) * 4; \
                    CP_ASYNC16(dst, B + (size_t)((kt) * 32 + row) * ldb + bn + c4 * 4); \
                }                                                             \
            }                                                                 \
        }                                                                     \
        CP_COMMIT();                                                          \
    }

    ISSUE(0);
    ISSUE(1);

    for (int kt = 0; kt < nk; ++kt) {
        CP_WAIT1();
        __syncthreads();

        const float* pa = sm + (kt % 3) * 8192;
        const float* pb = pa + 4096;

#pragma unroll
        for (int ks = 0; ks < 4; ++ks) {
            const int s0 = tig + (((2 * ks)     ^ gid) << 2);
            const int s1 = tig + (((2 * ks + 1) ^ gid) << 2);

            float af[4][4];
#pragma unroll
            for (int mt = 0; mt < 4; ++mt) {
                const int r0 = (wm + mt * 16 + gid) * 32;
                const int r1 = r0 + 256;
                af[mt][0] = pa[r0 + s0];
                af[mt][1] = pa[r1 + s0];
                af[mt][2] = pa[r0 + s1];
                af[mt][3] = pa[r1 + s1];
            }
            float bf[4][2];
#pragma unroll
            for (int nt = 0; nt < 4; ++nt) {
                if (BMODE == 0) {
                    const int nrow = (wn + nt * 8 + gid) * 32;
                    bf[nt][0] = pb[nrow + s0];
                    bf[nt][1] = pb[nrow + s1];
                } else {
                    bf[nt][0] = pb[b1off0[nt] + ks * 1024];
                    bf[nt][1] = pb[b1off1[nt] + ks * 1024];
                }
            }

            uint32_t ah[4][4], bh[4][2];
#pragma unroll
            for (int mt = 0; mt < 4; ++mt)
#pragma unroll
                for (int q = 0; q < 4; ++q) ah[mt][q] = f2tf(af[mt][q]);
#pragma unroll
            for (int nt = 0; nt < 4; ++nt) {
                bh[nt][0] = f2tf(bf[nt][0]);
                bh[nt][1] = f2tf(bf[nt][1]);
            }
#pragma unroll
            for (int mt = 0; mt < 4; ++mt)
#pragma unroll
                for (int nt = 0; nt < 4; ++nt)
                    mma_tf32(acc[mt][nt], ah[mt], bh[nt][0], bh[nt][1]);
        }
        ISSUE(kt + 2);
    }
#undef ISSUE

#pragma unroll
    for (int mt = 0; mt < 4; ++mt) {
#pragma unroll
        for (int half = 0; half < 2; ++half) {
            const long row = bm + wm + mt * 16 + gid + half * 8;
#pragma unroll
            for (int nt = 0; nt < 4; ++nt) {
                const int col = bn + wn + nt * 8 + 2 * tig;
                float v0 = acc[mt][nt][half * 2 + 0];
                float v1 = acc[mt][nt][half * 2 + 1];
                if (EPI == 1 || EPI == 3) {
                    v0 += bias[col];
                    v1 += bias[col + 1];
                }
                if (EPI == 3) {
                    const float2 rr = *(const float2*)&R[row * ldr + col];
                    v0 += rr.x; v1 += rr.y;
                }
                if (EPI == 2) {
                    const float2 av = *(const float2*)&A[row * (size_t)lda + col];
                    v0 = av.x * (1.f / (1.f + __expf(-v0)));
                    v1 = av.y * (1.f / (1.f + __expf(-v1)));
                }
                float2 o; o.x = v0; o.y = v1;
                *(float2*)&C[row * (size_t)ldc + col] = o;
            }
        }
    }
}

// =====================================================================
// Pre-split tf32 GEMM: C = A @ B^T with A,B given as (hi,lo) tf32 pairs.
// 3-term product (AhBh + AhBl + AlBh), ZERO cvt in the mainloop.
// Tiles 128x128x32, 256 thr, 3-stage cp.async of 4 tiles (64KB/stage).
// =====================================================================
__global__ void __launch_bounds__(256, 1)
sp_gemm(const float* __restrict__ Ahi, const float* __restrict__ Alo,
        const float* __restrict__ Bhi, const float* __restrict__ Blo,
        float* __restrict__ C, int M, int N, int K,
        int lda, int ldb, int ldc,
        long sA, long sB, long sC)
{
    Ahi += (long)blockIdx.z * sA;
    Alo += (long)blockIdx.z * sA;
    Bhi += (long)blockIdx.z * sB;
    Blo += (long)blockIdx.z * sB;
    C   += (long)blockIdx.z * sC;

    extern __shared__ float sm[];
    const uint32_t sbase = smem_u32(sm);

    const int tid  = threadIdx.x;
    const int lane = tid & 31;
    const int warp = tid >> 5;
    const int gid  = lane >> 2;
    const int tig  = lane & 3;
    const int wm   = (warp >> 2) * 64;
    const int wn   = (warp & 3) * 32;
    const int bm   = blockIdx.y * 128;
    const int bn   = blockIdx.x * 128;
    const int nk   = K >> 5;

    float acc[4][4][4];
#pragma unroll
    for (int mt = 0; mt < 4; ++mt)
#pragma unroll
        for (int nt = 0; nt < 4; ++nt)
#pragma unroll
            for (int q = 0; q < 4; ++q) acc[mt][nt][q] = 0.f;

    const int arow = tid >> 3, ac4 = tid & 7;

    // stage = 16384 floats: AH[0,4096) AL[4096,8192) BH[8192,12288) BL[12288,16384)
#define SP_ISSUE(kt)                                                          \
    {                                                                         \
        if ((kt) < nk) {                                                      \
            const uint32_t st = sbase + ((kt) % 3) * 65536;                   \
            _Pragma("unroll")                                                 \
            for (int i = 0; i < 4; ++i) {                                     \
                const int row = arow + 32 * i;                                \
                const uint32_t off = (uint32_t)(row * 32 + ((ac4 ^ (row & 7)) << 2)) * 4; \
                const size_t ga = (size_t)(bm + row) * lda + (kt) * 32 + ac4 * 4; \
                const size_t gb = (size_t)(bn + row) * ldb + (kt) * 32 + ac4 * 4; \
                CP_ASYNC16(st + off,         Ahi + ga);                       \
                CP_ASYNC16(st + 16384 + off, Alo + ga);                       \
                CP_ASYNC16(st + 32768 + off, Bhi + gb);                       \
                CP_ASYNC16(st + 49152 + off, Blo + gb);                       \
            }                                                                 \
        }                                                                     \
        CP_COMMIT();                                                          \
    }

    SP_ISSUE(0);
    SP_ISSUE(1);

    for (int kt = 0; kt < nk; ++kt) {
        CP_WAIT1();
        __syncthreads();

        const uint32_t* pah = (const uint32_t*)(sm + (kt % 3) * 16384);
        const uint32_t* pal = pah + 4096;
        const uint32_t* pbh = pah + 8192;
        const uint32_t* pbl = pah + 12288;

#pragma unroll
        for (int ks = 0; ks < 4; ++ks) {
            const int s0 = tig + (((2 * ks)     ^ gid) << 2);
            const int s1 = tig + (((2 * ks + 1) ^ gid) << 2);

            uint32_t ah[4][4], al[4][4];
#pragma unroll
            for (int mt = 0; mt < 4; ++mt) {
                const int r0 = (wm + mt * 16 + gid) * 32;
                const int r1 = r0 + 256;
                ah[mt][0] = pah[r0 + s0]; ah[mt][1] = pah[r1 + s0];
                ah[mt][2] = pah[r0 + s1]; ah[mt][3] = pah[r1 + s1];
                al[mt][0] = pal[r0 + s0]; al[mt][1] = pal[r1 + s0];
                al[mt][2] = pal[r0 + s1]; al[mt][3] = pal[r1 + s1];
            }
            uint32_t bh[4][2], bl[4][2];
#pragma unroll
            for (int nt = 0; nt < 4; ++nt) {
                const int nrow = (wn + nt * 8 + gid) * 32;
                bh[nt][0] = pbh[nrow + s0]; bh[nt][1] = pbh[nrow + s1];
                bl[nt][0] = pbl[nrow + s0]; bl[nt][1] = pbl[nrow + s1];
            }
#pragma unroll
            for (int mt = 0; mt < 4; ++mt)
#pragma unroll
                for (int nt = 0; nt < 4; ++nt) {
                    mma_tf32(acc[mt][nt], al[mt], bh[nt][0], bh[nt][1]);
                    mma_tf32(acc[mt][nt], ah[mt], bl[nt][0], bl[nt][1]);
                    mma_tf32(acc[mt][nt], ah[mt], bh[nt][0], bh[nt][1]);
                }
        }
        SP_ISSUE(kt + 2);
    }
#undef SP_ISSUE

#pragma unroll
    for (int mt = 0; mt < 4; ++mt) {
#pragma unroll
        for (int half = 0; half < 2; ++half) {
            const long row = bm + wm + mt * 16 + gid + half * 8;
#pragma unroll
            for (int nt = 0; nt < 4; ++nt) {
                const int col = bn + wn + nt * 8 + 2 * tig;
                float2 o;
                o.x = acc[mt][nt][half * 2 + 0];
                o.y = acc[mt][nt][half * 2 + 1];
                *(float2*)&C[row * (size_t)ldc + col] = o;
            }
        }
    }
}

// =====================================================================
// hi/lo tf32 decomposition: hi = rna(v), lo = rna(v - hi)
// =====================================================================
__global__ void hl_kernel(const float* __restrict__ in,
                          float* __restrict__ hi, float* __restrict__ lo, long n4)
{
    const long i = (long)blockIdx.x * 256 + threadIdx.x;
    if (i >= n4) return;
    const float4 v = ((const float4*)in)[i];
    float4 h, l;
    h.x = __uint_as_float(f2tf(v.x)); l.x = __uint_as_float(f2tf(v.x - h.x));
    h.y = __uint_as_float(f2tf(v.y)); l.y = __uint_as_float(f2tf(v.y - h.y));
    h.z = __uint_as_float(f2tf(v.z)); l.z = __uint_as_float(f2tf(v.z - h.z));
    h.w = __uint_as_float(f2tf(v.w)); l.w = __uint_as_float(f2tf(v.w - h.w));
    ((float4*)hi)[i] = h;
    ((float4*)lo)[i] = l;
}

// =====================================================================
// Generic 32x32 tiled transpose: out[c*R + r] = in[r*C + c]
// =====================================================================
__global__ void transpose_kernel(const float* __restrict__ in, float* __restrict__ out,
                                 int Rr, int Cc)
{
    __shared__ float t[32][33];
    const int c0 = blockIdx.x * 32;
    const int r0 = blockIdx.y * 32;
#pragma unroll
    for (int i = 0; i < 32; i += 8)
        t[threadIdx.y + i][threadIdx.x] =
            in[(size_t)(r0 + threadIdx.y + i) * Cc + c0 + threadIdx.x];
    __syncthreads();
#pragma unroll
    for (int i = 0; i < 32; i += 8)
        out[(size_t)(c0 + threadIdx.y + i) * Rr + r0 + threadIdx.x] =
            t[threadIdx.x][threadIdx.y + i];
}

// =====================================================================
// Row softmax over [B*S, S] with diagonal mask
// =====================================================================
__global__ void softmax_kernel(float* __restrict__ s)
{
    const long row = blockIdx.x;
    const int i = (int)(row & (SS - 1));
    float* p = s + row * SS;
    const int tid = threadIdx.x;

    float vals[8];
    float mx = -1e30f;
#pragma unroll
    for (int u = 0; u < 8; ++u) {
        const int j = tid + u * 256;
        float v = p[j];
        if (j == i) v = -INFINITY;
        vals[u] = v;
        mx = fmaxf(mx, v);
    }
    __shared__ float red[256];
    red[tid] = mx;
    __syncthreads();
#pragma unroll
    for (int st = 128; st; st >>= 1) {
        if (tid < st) red[tid] = fmaxf(red[tid], red[tid + st]);
        __syncthreads();
    }
    mx = red[0];
    __syncthreads();

    float sum = 0.f;
#pragma unroll
    for (int u = 0; u < 8; ++u) {
        vals[u] = __expf(vals[u] - mx);
        sum += vals[u];
    }
    red[tid] = sum;
    __syncthreads();
#pragma unroll
    for (int st = 128; st; st >>= 1) {
        if (tid < st) red[tid] += red[tid + st];
        __syncthreads();
    }
    const float inv = 1.f / red[0];
#pragma unroll
    for (int u = 0; u < 8; ++u) p[tid + u * 256] = vals[u] * inv;
}

__global__ void copy_x_kernel(const float* __restrict__ x, float* __restrict__ rinraw)
{
    const long i = (long)blockIdx.x * 256 + threadIdx.x;
    const long row = i >> 7;
    const long col = i & 127;
    ((float4*)rinraw)[row * (2 * DD / 4) + col] = ((const float4*)x)[i];
}

__global__ void init_kernel()
{
    const int t = blockIdx.x * 256 + threadIdx.x;
    float* h = &g_hT[0][0][0];
    if (t < 2 * 2 * HH * BB) h[t] = 0.f;
    unsigned* fl = &g_flag[0][0][0];
    if (t < 2 * 64 * 32) fl[t] = 0u;
}

// =====================================================================
// Persistent bidirectional GRU (R14/R16 proven config, unchanged):
//  - tensor-core recurrence dot (m16n8k8 tf32), weights in frags
//  - per-producer poll+copy streaming exchange, single-writer flags
//  - xw prefetch distance 2 (parity register sets)
// =====================================================================
#define CPB 64
#define HP 516   // padded smem row stride

__device__ __forceinline__ float fsig(float x)  { return 1.f / (1.f + __expf(-x)); }
__device__ __forceinline__ float ftanh(float x) { return 1.f - 2.f / (__expf(2.f * x) + 1.f); }

__global__ void __launch_bounds__(256, 1)
gru_kernel(const float* __restrict__ xwT_f, const float* __restrict__ xwT_b,
           const float* __restrict__ Whh_f, const float* __restrict__ Whh_b,
           const float* __restrict__ bhh_f, const float* __restrict__ bhh_b,
           float* __restrict__ hcatT)
{
    const int cta = blockIdx.x;
    const int dir = cta >> 6;
    const int slice = cta & 63;
    const float* xwT = dir ? xwT_b : xwT_f;
    const float* Whh = dir ? Whh_b : Whh_f;
    const float* bhh = dir ? bhh_b : bhh_f;

    const int tid = threadIdx.x;
    const int w = tid >> 5;
    const int lane = tid & 31;
    const int gid = lane >> 2;
    const int tig = lane & 3;

    __shared__ float smem_s[8 * HP + 8 * 192];
    float* h_s = smem_s;
    float* red = smem_s + 8 * HP;

    uint32_t bfr[3][8][2];
#pragma unroll
    for (int g = 0; g < 3; ++g)
#pragma unroll
        for (int kt = 0; kt < 8; ++kt) {
            const float* row = Whh + (size_t)(g * HH + slice * 8 + gid) * HH + w * 64 + kt * 8;
            bfr[g][kt][0] = f2tf(__ldg(row + tig));
            bfr[g][kt][1] = f2tf(__ldg(row + tig + 4));
        }

    const int t2 = tid;
    const int gb = t2 >> 3;
    const int gjl = t2 & 7;
    const int gj = slice * 8 + gjl;
    float br = 0.f, bz = 0.f, bnb = 0.f;
    const float *pr = nullptr, *pz = nullptr, *pn = nullptr;
    float* hout_base = nullptr;
    if (t2 < 64) {
        br = bhh[gj]; bz = bhh[HH + gj]; bnb = bhh[2 * HH + gj];
        pr = xwT + (size_t)gj * (BB * SS) + gb * SS;
        pz = xwT + (size_t)(HH + gj) * (BB * SS) + gb * SS;
        pn = xwT + (size_t)(2 * HH + gj) * (BB * SS) + gb * SS;
        hout_base = hcatT + (size_t)(dir * HH + gj) * (BB * SS) + gb * SS;
    }

    unsigned* myflag = &g_flag[dir][slice][0];
    const int cp_p = tid >> 2;
    const int cp_j0 = cp_p * 8 + (tid & 3) * 2;
    unsigned* cp_flag = &g_flag[dir][cp_p][0];

    float xr_e = 0.f, xz_e = 0.f, xn_e = 0.f;
    float xr_o = 0.f, xz_o = 0.f, xn_o = 0.f;
    if (t2 < 64) {
        const int t0 = dir ? (SS - 1) : 0;
        const int t1 = dir ? (SS - 2) : 1;
        xr_e = __ldg(pr + t0); xz_e = __ldg(pz + t0); xn_e = __ldg(pn + t0);
        xr_o = __ldg(pr + t1); xz_o = __ldg(pz + t1); xn_o = __ldg(pn + t1);
    }

    for (int step = 0; step < SS; ++step) {
        const int p = step & 1;
        const int tt = dir ? (SS - 1 - step) : step;

        if (step > 0) {
            const unsigned target = (unsigned)step;
            unsigned v;
            do {
                asm volatile("ld.acquire.gpu.u32 %0, [%1];" : "=r"(v) : "l"(cp_flag));
            } while (v < target);
        }
        {
            const float4* src = (const float4*)(&g_hT[p][dir][0]) + cp_j0 * 2;
            const float4 v0 = __ldcg(src);
            const float4 v1 = __ldcg(src + 1);
            const float4 v2 = __ldcg(src + 2);
            const float4 v3 = __ldcg(src + 3);
            *(float2*)&h_s[0 * HP + cp_j0] = make_float2(v0.x, v2.x);
            *(float2*)&h_s[1 * HP + cp_j0] = make_float2(v0.y, v2.y);
            *(float2*)&h_s[2 * HP + cp_j0] = make_float2(v0.z, v2.z);
            *(float2*)&h_s[3 * HP + cp_j0] = make_float2(v0.w, v2.w);
            *(float2*)&h_s[4 * HP + cp_j0] = make_float2(v1.x, v3.x);
            *(float2*)&h_s[5 * HP + cp_j0] = make_float2(v1.y, v3.y);
            *(float2*)&h_s[6 * HP + cp_j0] = make_float2(v1.z, v3.z);
            *(float2*)&h_s[7 * HP + cp_j0] = make_float2(v1.w, v3.w);
        }
        __syncthreads();

        float acc[3][4];
#pragma unroll
        for (int g = 0; g < 3; ++g)
#pragma unroll
            for (int q = 0; q < 4; ++q) acc[g][q] = 0.f;

#pragma unroll
        for (int kt = 0; kt < 8; ++kt) {
            const int k0 = w * 64 + kt * 8;
            uint32_t a[4];
            a[0] = f2tf(h_s[gid * HP + k0 + tig]);
            a[2] = f2tf(h_s[gid * HP + k0 + tig + 4]);
            a[1] = 0u;
            a[3] = 0u;
#pragma unroll
            for (int g = 0; g < 3; ++g)
                mma_tf32(acc[g], a, bfr[g][kt][0], bfr[g][kt][1]);
        }
#pragma unroll
        for (int g = 0; g < 3; ++g)
            *(float2*)&red[w * 192 + g * 64 + gid * 8 + 2 * tig] =
                make_float2(acc[g][0], acc[g][1]);

        float hprev = 0.f;
        if (t2 < 64) hprev = h_s[gb * HP + gj];
        __syncthreads();

        if (t2 < 64) {
            float gr = 0.f, gz = 0.f, gn = 0.f;
#pragma unroll
            for (int w2 = 0; w2 < 8; ++w2) {
                gr += red[w2 * 192 + t2];
                gz += red[w2 * 192 + 64 + t2];
                gn += red[w2 * 192 + 128 + t2];
            }
            const float xr_s = p ? xr_o : xr_e;
            const float xz_s = p ? xz_o : xz_e;
            const float xn_s = p ? xn_o : xn_e;
            const float r = fsig(xr_s + gr + br);
            const float z = fsig(xz_s + gz + bz);
            const float n = ftanh(xn_s + r * (gn + bnb));
            const float hn = (1.f - z) * n + z * hprev;
            g_hT[p ^ 1][dir][gj * 8 + gb] = hn;

            asm volatile("bar.sync 1, 64;" ::: "memory");
            if (tid == 0) {
                __threadfence();
                asm volatile("st.relaxed.gpu.u32 [%0], %1;"
                             :: "l"(myflag), "r"((unsigned)(step + 1)) : "memory");
            }

            hout_base[tt] = hn;
            if (step + 2 < SS) {
                const int tn_ = dir ? (SS - 3 - step) : (step + 2);
                if (p) {
                    xr_o = __ldg(pr + tn_); xz_o = __ldg(pz + tn_); xn_o = __ldg(pn + tn_);
                } else {
                    xr_e = __ldg(pr + tn_); xz_e = __ldg(pz + tn_); xn_e = __ldg(pn + tn_);
                }
            }
        }
    }
}

// =====================================================================
extern "C" void kernel_launch(void* const* d_in, const int* in_sizes, int n_in,
                              void* d_out, int out_size)
{
    (void)in_sizes; (void)n_in; (void)out_size;
    const float* x     = (const float*)d_in[0];
    const float* W     = (const float*)d_in[1];
    const float* Wg    = (const float*)d_in[2];
    const float* Wih_f = (const float*)d_in[3];
    const float* Whh_f = (const float*)d_in[4];
    const float* bih_f = (const float*)d_in[5];
    const float* bhh_f = (const float*)d_in[6];
    const float* Wih_b = (const float*)d_in[7];
    const float* Whh_b = (const float*)d_in[8];
    const float* bih_b = (const float*)d_in[9];
    const float* bhh_b = (const float*)d_in[10];
    const float* Wp    = (const float*)d_in[11];
    const float* bp    = (const float*)d_in[12];
    float* out = (float*)d_out;

    float *Wx, *sc, *rinraw, *rin, *xwf, *xwb, *xwfT, *xwbT, *hcat, *hcatT;
    float *xhi, *xlo, *whi, *wlo, *wxhi, *wxlo;
    cudaGetSymbolAddress((void**)&Wx,     g_Wx);
    cudaGetSymbolAddress((void**)&sc,     g_sc);
    cudaGetSymbolAddress((void**)&rinraw, g_rinraw);
    cudaGetSymbolAddress((void**)&rin,    g_rin);
    cudaGetSymbolAddress((void**)&xwf,    g_xwf);
    cudaGetSymbolAddress((void**)&xwb,    g_xwb);
    cudaGetSymbolAddress((void**)&xwfT,   g_xwfT);
    cudaGetSymbolAddress((void**)&xwbT,   g_xwbT);
    cudaGetSymbolAddress((void**)&hcat,   g_hcat);
    cudaGetSymbolAddress((void**)&hcatT,  g_hcatT);
    cudaGetSymbolAddress((void**)&xhi,    g_xhi);
    cudaGetSymbolAddress((void**)&xlo,    g_xlo);
    cudaGetSymbolAddress((void**)&whi,    g_whi);
    cudaGetSymbolAddress((void**)&wlo,    g_wlo);
    cudaGetSymbolAddress((void**)&wxhi,   g_wxhi);
    cudaGetSymbolAddress((void**)&wxlo,   g_wxlo);

    const int M = BB * SS;
    const int SMEM = 98304;      // pip_gemm: 3 stages x 32KB
    const int SPSMEM = 196608;   // sp_gemm:  3 stages x 64KB

    cudaFuncSetAttribute(sp_gemm,        cudaFuncAttributeMaxDynamicSharedMemorySize, SPSMEM);
    cudaFuncSetAttribute(pip_gemm<1, 0>, cudaFuncAttributeMaxDynamicSharedMemorySize, SMEM);
    cudaFuncSetAttribute(pip_gemm<0, 1>, cudaFuncAttributeMaxDynamicSharedMemorySize, SMEM);
    cudaFuncSetAttribute(pip_gemm<0, 2>, cudaFuncAttributeMaxDynamicSharedMemorySize, SMEM);
    cudaFuncSetAttribute(pip_gemm<0, 3>, cudaFuncAttributeMaxDynamicSharedMemorySize, SMEM);

    init_kernel<<<64, 256>>>();

    copy_x_kernel<<<(M * DD / 4) / 256, 256>>>(x, rinraw);

    // hi/lo decompositions for the score path
    hl_kernel<<<(M * DD / 4 + 255) / 256, 256>>>(x, xhi, xlo, (long)M * DD / 4);
    hl_kernel<<<(DD * DD / 4 + 255) / 256, 256>>>(W, whi, wlo, (long)DD * DD / 4);

    // Wx = x @ W^T (pre-split tf32, no cvt in mainloop)
    sp_gemm<<<dim3(DD / 128, M / 128, 1), 256, SPSMEM>>>(
        xhi, xlo, whi, wlo, Wx, M, DD, DD, DD, DD, DD, 0, 0, 0);

    hl_kernel<<<(M * DD / 4 + 255) / 256, 256>>>(Wx, wxhi, wxlo, (long)M * DD / 4);

    // s[b] = Wx[b] @ x[b]^T (pre-split tf32)
    sp_gemm<<<dim3(SS / 128, SS / 128, BB), 256, SPSMEM>>>(
        wxhi, wxlo, xhi, xlo, sc, SS, SS, DD, DD, DD, SS,
        (long)SS * DD, (long)SS * DD, (long)SS * SS);

    softmax_kernel<<<M, 256>>>(sc);

    // rin_raw[:, 512:] = a[b] @ x[b]   (tf32, BMODE1)
    pip_gemm<1, 0><<<dim3(DD / 128, SS / 128, BB), 256, SMEM>>>(
        sc, x, rinraw + DD, SS, DD, SS, SS, DD, 2 * DD,
        (long)SS * SS, (long)SS * DD, (long)SS * 2 * DD, nullptr, nullptr, 0);

    // rin = rin_raw * sigmoid(rin_raw @ Wg^T)
    pip_gemm<0, 2><<<dim3(2 * DD / 128, M / 128, 1), 256, SMEM>>>(
        rinraw, Wg, rin, M, 2 * DD, 2 * DD, 2 * DD, 2 * DD, 2 * DD,
        0, 0, 0, nullptr, nullptr, 0);

    // xw = rin @ Wih^T + bih (both directions)
    pip_gemm<0, 1><<<dim3(3 * HH / 128, M / 128, 1), 256, SMEM>>>(
        rin, Wih_f, xwf, M, 3 * HH, 2 * DD, 2 * DD, 2 * DD, 3 * HH,
        0, 0, 0, bih_f, nullptr, 0);
    pip_gemm<0, 1><<<dim3(3 * HH / 128, M / 128, 1), 256, SMEM>>>(
        rin, Wih_b, xwb, M, 3 * HH, 2 * DD, 2 * DD, 2 * DD, 3 * HH,
        0, 0, 0, bih_b, nullptr, 0);

    // transpose xw to [g*H+j][b*S+t] for streaming GRU loads
    transpose_kernel<<<dim3(3 * HH / 32, M / 32), dim3(32, 8)>>>(xwf, xwfT, M, 3 * HH);
    transpose_kernel<<<dim3(3 * HH / 32, M / 32), dim3(32, 8)>>>(xwb, xwbT, M, 3 * HH);

    // bidirectional GRU -> hcatT [2H][M]
    gru_kernel<<<128, 256>>>(xwfT, xwbT, Whh_f, Whh_b, bhh_f, bhh_b, hcatT);

    // transpose hcatT -> hcat [M][2H]
    transpose_kernel<<<dim3(M / 32, 2 * HH / 32), dim3(32, 8)>>>(hcatT, hcat, 2 * HH, M);

    // out = x + hcat @ Wp^T + bp
    pip_gemm<0, 3><<<dim3(DD / 128, M / 128, 1), 256, SMEM>>>(
        hcat, Wp, out, M, DD, 2 * HH, 2 * HH, 2 * HH, DD,
        0, 0, 0, bp, x, DD);
}